// round 11
// baseline (speedup 1.0000x reference)
#include <cuda_runtime.h>

// Problem constants
#define DD    128   // feature dim
#define CO    16    // output channels
#define PPV   16    // P*P
#define HG    32    // sqrt(N)
#define NB    32    // batch
#define NT    64    // n-rows per block
#define WTSEG 520   // floats per k-quarter segment of wsT (512 + 8 pad -> kq shifts 8 banks)
#define XWPAD 20    // xw row stride (floats): conflict-free phase-2 LDS.128

__device__ float g_cb[CO * PPV];        // emb[c].W[p] + bias[p], built once by k0

// ---------------------------------------------------------------------------
// k0: 1 block, 256 threads. cb[c][p] = emb[c].W[p] + bias[p].
// ---------------------------------------------------------------------------
__global__ void __launch_bounds__(256)
k0_cb(const float* __restrict__ emb,
      const float* __restrict__ W,
      const float* __restrict__ bias) {
    const int t = threadIdx.x;
    const int c = t >> 4, p = t & 15;
    const float4* e4 = reinterpret_cast<const float4*>(emb) + c * 32;
    const float4* w4 = reinterpret_cast<const float4*>(W) + p * 32;
    float acc = 0.f;
    #pragma unroll 8
    for (int i = 0; i < 32; i++) {
        float4 e = __ldg(&e4[i]);
        float4 v = __ldg(&w4[i]);
        acc += e.x * v.x + e.y * v.y + e.z * v.z + e.w * v.w;
    }
    g_cb[t] = acc + __ldg(&bias[p]);
}

// inline fn (NOT a macro: a macro param named like a float4 member gets
// token-substituted inside .x/.y/.z/.w accesses)
__device__ __forceinline__ void fma4(float4& acc, float s, const float4& v) {
    acc.x += s * v.x;
    acc.y += s * v.y;
    acc.z += s * v.z;
    acc.w += s * v.w;
}

// ---------------------------------------------------------------------------
// Main: one block per (n-tile=64, b). 256 threads, grid (16,32)=512.
//  Thread tile: 4 n-rows x 4 p (one patch-row pr, float4) x 1/4 of K.
//  Phase 0 : wsT (transposed W, float4[k][pr], 4 padded k-quarter segs),
//            cbs <- g_cb, mask.
//  Phase 1 : partial dots over own k-quarter (x via direct LDG);
//            shfl.xor(1),(2) combine k-quarters; kq==0 lanes STS y4 -> xw.
//  Phase 2 : (round-6 epilogue) 16 channel stores, 512B coalesced rows.
// ---------------------------------------------------------------------------
__global__ void __launch_bounds__(256, 4)
decoder_main(const float* __restrict__ x,
             const float* __restrict__ W,
             const float* __restrict__ mask,
             float* __restrict__ out) {
    __shared__ float wsT[4 * WTSEG];     //  8,320 B : wsT[kq][k_local][pr] float4
    __shared__ float xw[NT * XWPAD];     //  5,120 B
    __shared__ float cbs[CO * PPV];      //  1,024 B
    __shared__ float ms[CO];             //     64 B

    const int t  = threadIdx.x;
    const int nt = blockIdx.x;           // 0..15
    const int b  = blockIdx.y;           // 0..31

    // ---- Phase 0 --------------------------------------------------------
    {
        // transpose W into wsT: entry (k, pr) = float4(W[4pr+u][k], u=0..3)
        #pragma unroll
        for (int kk = 0; kk < 2; kk++) {
            int j  = t + kk * 256;       // 0..511
            int k  = j >> 2;             // 0..127
            int pr = j & 3;
            float* dst = &wsT[(k >> 5) * WTSEG + (k & 31) * 16 + pr * 4];
            #pragma unroll
            for (int u = 0; u < 4; u++)
                dst[u] = __ldg(&W[(4 * pr + u) * DD + k]);
        }
        cbs[t] = g_cb[t];                // 256 threads == 256 entries
        if (t < CO) ms[t] = mask[b * CO + t];
    }
    __syncthreads();

    // ---- Phase 1: 4n x 4p x k-quarter partial GEMV ----------------------
    {
        const int kq   = t & 3;          // k quarter (lane bits 0..1)
        const int pgrp = (t >> 2) & 3;   // patch row pr (lane bits 2..3)
        const int ng   = t >> 4;         // 0..15 : 4-row group

        const int n0 = ng * 4;           // local base row
        const float4* xp = reinterpret_cast<const float4*>(x)
                         + ((size_t)b * 1024 + (size_t)nt * NT + n0) * 32 + kq * 8;
        const float* wseg = &wsT[kq * WTSEG + pgrp * 4];

        float4 acc0 = {0,0,0,0}, acc1 = {0,0,0,0}, acc2 = {0,0,0,0}, acc3 = {0,0,0,0};
        #pragma unroll 4
        for (int ch = 0; ch < 8; ch++) { // 4 k-scalars per chunk
            float4 xa0 = __ldg(xp + 0 * 32 + ch);
            float4 xa1 = __ldg(xp + 1 * 32 + ch);
            float4 xa2 = __ldg(xp + 2 * 32 + ch);
            float4 xa3 = __ldg(xp + 3 * 32 + ch);
            float4 w0 = *reinterpret_cast<const float4*>(wseg + (ch * 4 + 0) * 16);
            float4 w1 = *reinterpret_cast<const float4*>(wseg + (ch * 4 + 1) * 16);
            float4 w2 = *reinterpret_cast<const float4*>(wseg + (ch * 4 + 2) * 16);
            float4 w3 = *reinterpret_cast<const float4*>(wseg + (ch * 4 + 3) * 16);
            fma4(acc0, xa0.x, w0); fma4(acc0, xa0.y, w1); fma4(acc0, xa0.z, w2); fma4(acc0, xa0.w, w3);
            fma4(acc1, xa1.x, w0); fma4(acc1, xa1.y, w1); fma4(acc1, xa1.z, w2); fma4(acc1, xa1.w, w3);
            fma4(acc2, xa2.x, w0); fma4(acc2, xa2.y, w1); fma4(acc2, xa2.z, w2); fma4(acc2, xa2.w, w3);
            fma4(acc3, xa3.x, w0); fma4(acc3, xa3.y, w1); fma4(acc3, xa3.z, w2); fma4(acc3, xa3.w, w3);
        }

        // combine the 4 k-quarters (lanes differing in bits 0..1)
        float4* accs[4] = {&acc0, &acc1, &acc2, &acc3};
        #pragma unroll
        for (int r = 0; r < 4; r++) {
            float* a = reinterpret_cast<float*>(accs[r]);
            #pragma unroll
            for (int u = 0; u < 4; u++) {
                a[u] += __shfl_xor_sync(0xffffffffu, a[u], 1);
                a[u] += __shfl_xor_sync(0xffffffffu, a[u], 2);
            }
        }
        if (kq == 0) {
            #pragma unroll
            for (int r = 0; r < 4; r++)
                *reinterpret_cast<float4*>(&xw[(n0 + r) * XWPAD + pgrp * 4]) = *accs[r];
        }
    }
    __syncthreads();

    // ---- Phase 2: broadcast over channels, mask, store ------------------
    {
        const int rr    = t >> 5;        // 0..7 : image row within block
        const int hl    = rr >> 2;       // 0..1
        const int pr    = rr & 3;        // patch row
        const int colf4 = t & 31;        // lane = float4 along width

        const int n_local = hl * 32 + colf4;
        const float4 y4 = *reinterpret_cast<const float4*>(
            &xw[n_local * XWPAD + pr * 4]);

        const int grow = (nt * 2 + hl) * 4 + pr;
        float* ob = out + (((size_t)b * CO) * 128 + grow) * 128 + colf4 * 4;

        #pragma unroll
        for (int cb4i = 0; cb4i < 4; cb4i++) {
            float4 o[4];
            #pragma unroll
            for (int u = 0; u < 4; u++) {
                int c = cb4i * 4 + u;
                float4 cb4 = *reinterpret_cast<const float4*>(&cbs[c * PPV + pr * 4]);
                float  m   = ms[c];
                o[u].x = (y4.x + cb4.x) * m;
                o[u].y = (y4.y + cb4.y) * m;
                o[u].z = (y4.z + cb4.z) * m;
                o[u].w = (y4.w + cb4.w) * m;
            }
            #pragma unroll
            for (int u = 0; u < 4; u++) {
                int c = cb4i * 4 + u;
                *reinterpret_cast<float4*>(ob + (size_t)c * (128 * 128)) = o[u];
            }
        }
    }
}

// ---------------------------------------------------------------------------
extern "C" void kernel_launch(void* const* d_in, const int* in_sizes, int n_in,
                              void* d_out, int out_size) {
    const float* x    = (const float*)d_in[0];   // (32, 1024, 128)
    const float* mask = (const float*)d_in[1];   // (32, 16)
    const float* emb  = (const float*)d_in[2];   // (256, 128)
    const float* W    = (const float*)d_in[3];   // (16, 128)
    const float* bias = (const float*)d_in[4];   // (16,)
    float* out = (float*)d_out;                  // (32, 16, 128, 128)

    k0_cb<<<1, 256>>>(emb, W, bias);
    dim3 grid(HG * HG / NT, NB);                 // (16, 32) = 512 blocks
    decoder_main<<<grid, 256>>>(x, W, mask, out);
}

// round 14
// speedup vs baseline: 1.4314x; 1.4314x over previous
#include <cuda_runtime.h>

// Problem constants
#define DD    128   // feature dim
#define CO    16    // output channels
#define PPV   16    // P*P
#define HG    32    // sqrt(N)
#define NB    32    // batch
#define NT    64    // n-rows per block
#define WRS   33    // W smem row stride in float4 (32 + 1 pad)
#define XWPAD 20    // xw row stride (floats): conflict-free phase-2 LDS.128

__device__ __forceinline__ float dot4(const float4 a, const float4 b) {
    return a.x * b.x + a.y * b.y + a.z * b.z + a.w * b.w;
}

// ---------------------------------------------------------------------------
// Single kernel. One block per (n-tile=64, b). 256 threads, grid (16,32)=512.
//  Phase 0 : W -> smem, natural rows padded to 33 float4 (coalesced LDG).
//  Phase 1 : GEMV, thread tile 4n x 4p x 1/4 K (k INTERLEAVED: f = 4ch+kq ->
//            x LDG contiguous across kq lanes). shfl.xor(1),(2) combines kq.
//  Phase 1b: threads<128 compute cb[c][p]=emb[c].W[p]+bias[p] (2 dots each).
//  Phase 2 : 16-channel broadcast epilogue, 512B coalesced row stores.
// ---------------------------------------------------------------------------
__global__ void __launch_bounds__(256, 4)
decoder_one(const float* __restrict__ x,
            const float* __restrict__ W,
            const float* __restrict__ emb,
            const float* __restrict__ bias,
            const float* __restrict__ mask,
            float* __restrict__ out) {
    __shared__ float4 ws[PPV * WRS];     //  8,448 B : row p = ws[p*33 + f], f=0..31
    __shared__ float  xw[NT * XWPAD];    //  5,120 B
    __shared__ float  cbs[CO * PPV];     //  1,024 B
    __shared__ float  ms[CO];            //     64 B

    const int t  = threadIdx.x;
    const int nt = blockIdx.x;           // 0..15
    const int b  = blockIdx.y;           // 0..31

    // ---- Phase 0: coalesced W load -------------------------------------
    {
        const float4* wg4 = reinterpret_cast<const float4*>(W);
        #pragma unroll
        for (int kk = 0; kk < 2; kk++) {
            int j = t + kk * 256;        // 0..511
            ws[(j >> 5) * WRS + (j & 31)] = wg4[j];
        }
        if (t < CO) ms[t] = mask[b * CO + t];
    }
    __syncthreads();

    // ---- Phase 1: GEMV 4n x 4p, interleaved k-quarter -------------------
    {
        const int kq   = t & 3;          // lane bits 0..1 : k interleave
        const int pgrp = (t >> 2) & 3;   // lane bits 2..3 : patch row
        const int ng   = t >> 4;         // 0..15 : 4-row group
        const int n0   = ng * 4;

        // x float4 index for row r, chunk ch:  row*32 + 4*ch + kq
        const float4* xp = reinterpret_cast<const float4*>(x)
                         + ((size_t)b * 1024 + (size_t)nt * NT + n0) * 32 + kq;
        const float4* wp = &ws[(4 * pgrp) * WRS + kq];

        float acc[4][4];                 // [r][u]
        #pragma unroll
        for (int r = 0; r < 4; r++)
            #pragma unroll
            for (int u = 0; u < 4; u++) acc[r][u] = 0.f;

        #pragma unroll 4
        for (int ch = 0; ch < 8; ch++) {
            float4 xa0 = __ldg(xp + 0 * 32 + ch * 4);
            float4 xa1 = __ldg(xp + 1 * 32 + ch * 4);
            float4 xa2 = __ldg(xp + 2 * 32 + ch * 4);
            float4 xa3 = __ldg(xp + 3 * 32 + ch * 4);
            float4 w0 = wp[0 * WRS + ch * 4];
            float4 w1 = wp[1 * WRS + ch * 4];
            float4 w2 = wp[2 * WRS + ch * 4];
            float4 w3 = wp[3 * WRS + ch * 4];
            acc[0][0] += dot4(xa0, w0); acc[0][1] += dot4(xa0, w1);
            acc[0][2] += dot4(xa0, w2); acc[0][3] += dot4(xa0, w3);
            acc[1][0] += dot4(xa1, w0); acc[1][1] += dot4(xa1, w1);
            acc[1][2] += dot4(xa1, w2); acc[1][3] += dot4(xa1, w3);
            acc[2][0] += dot4(xa2, w0); acc[2][1] += dot4(xa2, w1);
            acc[2][2] += dot4(xa2, w2); acc[2][3] += dot4(xa2, w3);
            acc[3][0] += dot4(xa3, w0); acc[3][1] += dot4(xa3, w1);
            acc[3][2] += dot4(xa3, w2); acc[3][3] += dot4(xa3, w3);
        }

        // combine the 4 kq lanes (xor over lane bits 0..1)
        #pragma unroll
        for (int r = 0; r < 4; r++)
            #pragma unroll
            for (int u = 0; u < 4; u++) {
                acc[r][u] += __shfl_xor_sync(0xffffffffu, acc[r][u], 1);
                acc[r][u] += __shfl_xor_sync(0xffffffffu, acc[r][u], 2);
            }

        if (kq == 0) {
            #pragma unroll
            for (int r = 0; r < 4; r++) {
                float4 v = make_float4(acc[r][0], acc[r][1], acc[r][2], acc[r][3]);
                *reinterpret_cast<float4*>(&xw[(n0 + r) * XWPAD + pgrp * 4]) = v;
            }
        }
    }

    // ---- Phase 1b: cb[c][p] for threads < 128 (2 p per thread) ----------
    if (t < 128) {
        const int c  = t >> 3;           // 0..15
        const int pg = t & 7;            // p in {pg, pg+8}
        const float4* eg = reinterpret_cast<const float4*>(emb) + c * 32;
        float a0 = 0.f, a1 = 0.f;
        #pragma unroll 4
        for (int i = 0; i < 32; i++) {
            float4 e  = __ldg(eg + i);
            a0 += dot4(e, ws[pg * WRS + i]);
            a1 += dot4(e, ws[(pg + 8) * WRS + i]);
        }
        cbs[c * PPV + pg]     = a0 + __ldg(&bias[pg]);
        cbs[c * PPV + pg + 8] = a1 + __ldg(&bias[pg + 8]);
    }
    __syncthreads();

    // ---- Phase 2: broadcast over channels, mask, store ------------------
    {
        const int rr    = t >> 5;        // 0..7 : image row within block
        const int hl    = rr >> 2;       // 0..1
        const int pr    = rr & 3;        // patch row
        const int colf4 = t & 31;        // lane = float4 along width

        const int n_local = hl * 32 + colf4;
        const float4 y4 = *reinterpret_cast<const float4*>(
            &xw[n_local * XWPAD + pr * 4]);

        const int grow = (nt * 2 + hl) * 4 + pr;
        float* ob = out + (((size_t)b * CO) * 128 + grow) * 128 + colf4 * 4;

        #pragma unroll
        for (int cb4i = 0; cb4i < 4; cb4i++) {
            float4 o[4];
            #pragma unroll
            for (int u = 0; u < 4; u++) {
                int c = cb4i * 4 + u;
                float4 cb4 = *reinterpret_cast<const float4*>(&cbs[c * PPV + pr * 4]);
                float  m   = ms[c];
                o[u].x = (y4.x + cb4.x) * m;
                o[u].y = (y4.y + cb4.y) * m;
                o[u].z = (y4.z + cb4.z) * m;
                o[u].w = (y4.w + cb4.w) * m;
            }
            #pragma unroll
            for (int u = 0; u < 4; u++) {
                int c = cb4i * 4 + u;
                *reinterpret_cast<float4*>(ob + (size_t)c * (128 * 128)) = o[u];
            }
        }
    }
}

// ---------------------------------------------------------------------------
extern "C" void kernel_launch(void* const* d_in, const int* in_sizes, int n_in,
                              void* d_out, int out_size) {
    const float* x    = (const float*)d_in[0];   // (32, 1024, 128)
    const float* mask = (const float*)d_in[1];   // (32, 16)
    const float* emb  = (const float*)d_in[2];   // (256, 128)
    const float* W    = (const float*)d_in[3];   // (16, 128)
    const float* bias = (const float*)d_in[4];   // (16,)
    float* out = (float*)d_out;                  // (32, 16, 128, 128)

    dim3 grid(HG * HG / NT, NB);                 // (16, 32) = 512 blocks
    decoder_one<<<grid, 256>>>(x, W, emb, bias, mask, out);
}

// round 16
// speedup vs baseline: 1.4459x; 1.0101x over previous
#include <cuda_runtime.h>

// Problem constants
#define DD    128   // feature dim
#define CO    16    // output channels
#define PPV   16    // P*P
#define HG    32    // sqrt(N)
#define NB    32    // batch
#define NT    64    // n-rows per block
#define WRS   33    // W smem row stride in float4 (32 + 1 pad)
#define XWPAD 20    // xw row stride (floats): conflict-free phase-2 LDS.128

// packed fp32x2 FMA (sm_103a; PTX-only -- ptxas never auto-fuses)
__device__ __forceinline__ void ffma2(unsigned long long& d,
                                      unsigned long long a,
                                      unsigned long long b) {
    asm("fma.rn.f32x2 %0, %1, %2, %0;" : "+l"(d) : "l"(a), "l"(b));
}
__device__ __forceinline__ float hsum2(unsigned long long v) {
    float lo = __uint_as_float((unsigned)(v & 0xffffffffull));
    float hi = __uint_as_float((unsigned)(v >> 32));
    return lo + hi;
}

// ---------------------------------------------------------------------------
// Single kernel. One block per (n-tile=64, b). 256 threads, grid (16,32)=512.
//  Phase 0 : W -> smem, natural rows padded to 33 float4 (coalesced LDG).
//  Phase 1 : GEMV 4n x 4p x 1/4 K (k interleaved), fp32x2 packed FMA;
//            shfl.xor(1),(2) combines kq lanes; kq==0 stores to xw.
//  Phase 1b: ALL 256 threads: cb[c][p] = emb[c].W[p] + bias[p] (1 dot each,
//            packed). Then cbs *= mask -> premultiplied cbm table.
//  Phase 2 : o = fmaf(y, m, cbm): 1 FFMA/element; 512B coalesced row stores.
// ---------------------------------------------------------------------------
__global__ void __launch_bounds__(256, 3)
decoder_one(const float* __restrict__ x,
            const float* __restrict__ W,
            const float* __restrict__ emb,
            const float* __restrict__ bias,
            const float* __restrict__ mask,
            float* __restrict__ out) {
    __shared__ float4 ws[PPV * WRS];     //  8,448 B
    __shared__ float  xw[NT * XWPAD];    //  5,120 B
    __shared__ float  cbs[CO * PPV];     //  1,024 B
    __shared__ float  ms[CO];            //     64 B

    const int t  = threadIdx.x;
    const int nt = blockIdx.x;           // 0..15
    const int b  = blockIdx.y;           // 0..31

    // ---- Phase 0: coalesced W load -------------------------------------
    {
        const float4* wg4 = reinterpret_cast<const float4*>(W);
        #pragma unroll
        for (int kk = 0; kk < 2; kk++) {
            int j = t + kk * 256;        // 0..511
            ws[(j >> 5) * WRS + (j & 31)] = wg4[j];
        }
        if (t < CO) ms[t] = mask[b * CO + t];
    }
    __syncthreads();

    // ---- Phase 1: GEMV 4n x 4p, interleaved k-quarter, packed FMA -------
    {
        const int kq   = t & 3;          // lane bits 0..1 : k interleave
        const int pgrp = (t >> 2) & 3;   // lane bits 2..3 : patch row
        const int ng   = t >> 4;         // 0..15 : 4-row group
        const int n0   = ng * 4;

        // x row = 32 x 16B chunks; chunk index for (row, ch) = row*32 + 4*ch + kq
        const ulonglong2* xp = reinterpret_cast<const ulonglong2*>(
            x + ((size_t)b * 1024 + (size_t)nt * NT + n0) * DD) + kq;
        const ulonglong2* wp = reinterpret_cast<const ulonglong2*>(
            &ws[(4 * pgrp) * WRS + kq]);

        unsigned long long acc[4][4];    // [r][u], each = 2 packed partial sums
        #pragma unroll
        for (int r = 0; r < 4; r++)
            #pragma unroll
            for (int u = 0; u < 4; u++) acc[r][u] = 0ull;

        #pragma unroll 4
        for (int ch = 0; ch < 8; ch++) {
            ulonglong2 xa0 = __ldg(xp + 0 * 32 + ch * 4);
            ulonglong2 xa1 = __ldg(xp + 1 * 32 + ch * 4);
            ulonglong2 xa2 = __ldg(xp + 2 * 32 + ch * 4);
            ulonglong2 xa3 = __ldg(xp + 3 * 32 + ch * 4);
            ulonglong2 w0 = wp[0 * WRS + ch * 4];
            ulonglong2 w1 = wp[1 * WRS + ch * 4];
            ulonglong2 w2 = wp[2 * WRS + ch * 4];
            ulonglong2 w3 = wp[3 * WRS + ch * 4];
            ffma2(acc[0][0], xa0.x, w0.x); ffma2(acc[0][0], xa0.y, w0.y);
            ffma2(acc[0][1], xa0.x, w1.x); ffma2(acc[0][1], xa0.y, w1.y);
            ffma2(acc[0][2], xa0.x, w2.x); ffma2(acc[0][2], xa0.y, w2.y);
            ffma2(acc[0][3], xa0.x, w3.x); ffma2(acc[0][3], xa0.y, w3.y);
            ffma2(acc[1][0], xa1.x, w0.x); ffma2(acc[1][0], xa1.y, w0.y);
            ffma2(acc[1][1], xa1.x, w1.x); ffma2(acc[1][1], xa1.y, w1.y);
            ffma2(acc[1][2], xa1.x, w2.x); ffma2(acc[1][2], xa1.y, w2.y);
            ffma2(acc[1][3], xa1.x, w3.x); ffma2(acc[1][3], xa1.y, w3.y);
            ffma2(acc[2][0], xa2.x, w0.x); ffma2(acc[2][0], xa2.y, w0.y);
            ffma2(acc[2][1], xa2.x, w1.x); ffma2(acc[2][1], xa2.y, w1.y);
            ffma2(acc[2][2], xa2.x, w2.x); ffma2(acc[2][2], xa2.y, w2.y);
            ffma2(acc[2][3], xa2.x, w3.x); ffma2(acc[2][3], xa2.y, w3.y);
            ffma2(acc[3][0], xa3.x, w0.x); ffma2(acc[3][0], xa3.y, w0.y);
            ffma2(acc[3][1], xa3.x, w1.x); ffma2(acc[3][1], xa3.y, w1.y);
            ffma2(acc[3][2], xa3.x, w2.x); ffma2(acc[3][2], xa3.y, w2.y);
            ffma2(acc[3][3], xa3.x, w3.x); ffma2(acc[3][3], xa3.y, w3.y);
        }

        // reduce packed halves, then combine the 4 kq lanes (xor bits 0..1)
        #pragma unroll
        for (int r = 0; r < 4; r++) {
            float v[4];
            #pragma unroll
            for (int u = 0; u < 4; u++) {
                v[u] = hsum2(acc[r][u]);
                v[u] += __shfl_xor_sync(0xffffffffu, v[u], 1);
                v[u] += __shfl_xor_sync(0xffffffffu, v[u], 2);
            }
            if (kq == 0) {
                const int n0l = (t >> 4) * 4;
                *reinterpret_cast<float4*>(&xw[(n0l + r) * XWPAD + ((t >> 2) & 3) * 4]) =
                    make_float4(v[0], v[1], v[2], v[3]);
            }
        }
    }

    // ---- Phase 1b: cb[c][p], 1 dot per thread (all 256), packed ---------
    {
        const int c = t >> 4;            // 0..15
        const int p = t & 15;            // 0..15
        const ulonglong2* eg = reinterpret_cast<const ulonglong2*>(emb + c * DD);
        const ulonglong2* wp2 = reinterpret_cast<const ulonglong2*>(&ws[p * WRS]);
        unsigned long long a = 0ull;
        #pragma unroll 8
        for (int i = 0; i < 32; i++) {   // 32 x 16B per row
            ulonglong2 e = __ldg(eg + i);
            ulonglong2 w = wp2[i];
            ffma2(a, e.x, w.x);
            ffma2(a, e.y, w.y);
        }
        cbs[t] = hsum2(a) + __ldg(&bias[p]);
    }
    __syncthreads();

    // premultiply by mask: cbm[c][p] = cb[c][p] * m[c]  (in place, t->t safe)
    cbs[t] *= ms[t >> 4];
    __syncthreads();

    // ---- Phase 2: o = y*m + cbm  (1 FFMA per element) -------------------
    {
        const int rr    = t >> 5;        // 0..7 : image row within block
        const int hl    = rr >> 2;       // 0..1
        const int pr    = rr & 3;        // patch row
        const int colf4 = t & 31;        // lane = float4 along width

        const int n_local = hl * 32 + colf4;
        const float4 y4 = *reinterpret_cast<const float4*>(
            &xw[n_local * XWPAD + pr * 4]);

        const int grow = (nt * 2 + hl) * 4 + pr;
        float* ob = out + (((size_t)b * CO) * 128 + grow) * 128 + colf4 * 4;

        #pragma unroll
        for (int cb4i = 0; cb4i < 4; cb4i++) {
            float4 o[4];
            #pragma unroll
            for (int u = 0; u < 4; u++) {
                int c = cb4i * 4 + u;
                float4 cbm4 = *reinterpret_cast<const float4*>(&cbs[c * PPV + pr * 4]);
                float  m    = ms[c];
                o[u].x = fmaf(y4.x, m, cbm4.x);
                o[u].y = fmaf(y4.y, m, cbm4.y);
                o[u].z = fmaf(y4.z, m, cbm4.z);
                o[u].w = fmaf(y4.w, m, cbm4.w);
            }
            #pragma unroll
            for (int u = 0; u < 4; u++) {
                int c = cb4i * 4 + u;
                *reinterpret_cast<float4*>(ob + (size_t)c * (128 * 128)) = o[u];
            }
        }
    }
}

// ---------------------------------------------------------------------------
extern "C" void kernel_launch(void* const* d_in, const int* in_sizes, int n_in,
                              void* d_out, int out_size) {
    const float* x    = (const float*)d_in[0];   // (32, 1024, 128)
    const float* mask = (const float*)d_in[1];   // (32, 16)
    const float* emb  = (const float*)d_in[2];   // (256, 128)
    const float* W    = (const float*)d_in[3];   // (16, 128)
    const float* bias = (const float*)d_in[4];   // (16,)
    float* out = (float*)d_out;                  // (32, 16, 128, 128)

    dim3 grid(HG * HG / NT, NB);                 // (16, 32) = 512 blocks
    decoder_one<<<grid, 256>>>(x, W, emb, bias, mask, out);
}